// round 2
// baseline (speedup 1.0000x reference)
#include <cuda_runtime.h>
#include <cstdint>

#define N_NODES 100000
#define N_EDGES 3200000
#define F_IN 64
#define HID 20
#define N_GRAPHS 128
#define N_CLASSES 10
#define EPS_NORM 1e-12f

#define E_PAD (N_EDGES + N_NODES)   // room for 1 pad slot per node

// ---------------- scratch (device globals) ---------------------------------
__device__ __align__(16) float g_bufA[N_NODES * HID];
__device__ __align__(16) float g_bufB[N_NODES * HID];
__device__ __align__(16) float g_h[N_NODES * HID];
__device__ __align__(16) int2  g_edge[E_PAD];        // (src, w bits), sorted by dst
__device__ int g_deg[N_NODES];
__device__ int g_rowptr[N_NODES + 1];
__device__ int g_cursor[N_NODES];
__device__ float g_pmax[N_GRAPHS * HID];
__device__ float g_psum[N_GRAPHS * HID];
__device__ float g_cnt[N_GRAPHS];
__device__ int   g_is64;

// ---------------- dtype probe ----------------------------------------------
__global__ void k_detect(const void* __restrict__ ei) {
    if (threadIdx.x == 0 && blockIdx.x == 0) {
        const long long* p = (const long long*)ei;
        bool ok = true;
        #pragma unroll
        for (int i = 0; i < 16; i++) {
            long long v = p[i];
            if (v < 0 || v >= (long long)N_NODES) ok = false;
        }
        g_is64 = ok ? 1 : 0;
    }
}

// ---------------- CSR build -------------------------------------------------
__global__ void k_zero_deg() {
    int i = blockIdx.x * blockDim.x + threadIdx.x;
    if (i < N_NODES) g_deg[i] = 0;
}

__global__ void k_hist(const void* __restrict__ ei) {
    int e = blockIdx.x * blockDim.x + threadIdx.x;
    if (e >= N_EDGES) return;
    int d;
    if (g_is64) d = (int)((const long long*)ei)[N_EDGES + e];
    else        d = ((const int*)ei)[N_EDGES + e];
    atomicAdd(&g_deg[d], 1);
}

// single block, 1024 threads: exclusive scan of padded degrees
__global__ void k_scan() {
    __shared__ int s[1024];
    const int per = (N_NODES + 1023) / 1024;   // 98
    int t = threadIdx.x;
    int lo = t * per;
    int hi = lo + per; if (hi > N_NODES) hi = N_NODES;
    if (lo > N_NODES) lo = N_NODES;
    int sum = 0;
    for (int i = lo; i < hi; i++) sum += (g_deg[i] + 1) & ~1;
    s[t] = sum;
    __syncthreads();
    for (int off = 1; off < 1024; off <<= 1) {
        int v = (t >= off) ? s[t - off] : 0;
        __syncthreads();
        if (t >= off) s[t] += v;
        __syncthreads();
    }
    int run = (t == 0) ? 0 : s[t - 1];
    for (int i = lo; i < hi; i++) {
        g_rowptr[i] = run;
        g_cursor[i] = run;
        run += (g_deg[i] + 1) & ~1;
    }
    if (t == 1023) g_rowptr[N_NODES] = run;
}

__global__ void k_fill(const void* __restrict__ ei, const float* __restrict__ w) {
    int e = blockIdx.x * blockDim.x + threadIdx.x;
    if (e >= N_EDGES) return;
    int s, d;
    if (g_is64) {
        const long long* p = (const long long*)ei;
        s = (int)p[e]; d = (int)p[N_EDGES + e];
    } else {
        const int* p = (const int*)ei;
        s = p[e]; d = p[N_EDGES + e];
    }
    int pos = atomicAdd(&g_cursor[d], 1);
    g_edge[pos] = make_int2(s, __float_as_int(w[e]));
}

__global__ void k_pad() {
    int n = blockIdx.x * blockDim.x + threadIdx.x;
    if (n >= N_NODES) return;
    int deg = g_deg[n];
    if (deg & 1) g_edge[g_rowptr[n] + deg] = make_int2(0, 0);  // w=0 dummy
}

// ---------------- layer-1 input GEMM: bufA = x @ W1a ------------------------
#define GEMM_NPB 12
__global__ void k_gemm_in(const float* __restrict__ x, const float* __restrict__ W) {
    __shared__ float Ws[F_IN * HID];
    __shared__ float xs[GEMM_NPB * F_IN];
    int tid = threadIdx.x;
    for (int i = tid; i < F_IN * HID; i += blockDim.x) Ws[i] = W[i];
    int nbase = blockIdx.x * GEMM_NPB;
    int cnt = N_NODES - nbase; if (cnt > GEMM_NPB) cnt = GEMM_NPB;
    for (int i = tid; i < cnt * F_IN; i += blockDim.x) xs[i] = x[nbase * F_IN + i];
    __syncthreads();
    if (tid < cnt * HID) {
        int ln = tid / HID, f = tid % HID;
        float acc = 0.0f;
        #pragma unroll
        for (int k = 0; k < F_IN; k++) acc += xs[ln * F_IN + k] * Ws[k * HID + f];
        g_bufA[nbase * HID + tid] = acc;
    }
}

// ---------------- fused gather-aggregate + node MLP -------------------------
// mode: 0 = A->B, 1 = B->A, 2 = A->h (final layer; Wn unused)
__global__ void k_aggmlp(const float* __restrict__ ba, const float* __restrict__ Wb,
                         const float* __restrict__ bb, const float* __restrict__ Wn,
                         int mode) {
    __shared__ float sWb[HID * HID], sWn[HID * HID], sba[HID], sbb[HID];
    int tid = threadIdx.x;
    for (int i = tid; i < HID * HID; i += blockDim.x) {
        sWb[i] = Wb[i];
        sWn[i] = Wn ? Wn[i] : 0.0f;
    }
    if (tid < HID) { sba[tid] = ba[tid]; sbb[tid] = bb[tid]; }
    __syncthreads();

    int n = blockIdx.x * blockDim.x + tid;
    if (n >= N_NODES) return;

    const float* in  = (mode == 1) ? g_bufB : g_bufA;
    float* outp      = (mode == 0) ? g_bufB : ((mode == 1) ? g_bufA : g_h);

    int rs = g_rowptr[n], re = g_rowptr[n + 1];

    float acc[HID];
    #pragma unroll
    for (int k = 0; k < HID; k++) acc[k] = 0.0f;

    for (int e = rs; e < re; e += 2) {                 // rows padded to even
        int4 p = *(const int4*)&g_edge[e];             // two edges
        float w0 = __int_as_float(p.y);
        float w1 = __int_as_float(p.w);
        const float4* r0 = (const float4*)(in + p.x * HID);
        const float4* r1 = (const float4*)(in + p.z * HID);
        #pragma unroll
        for (int i = 0; i < 5; i++) {
            float4 a = __ldg(r0 + i);
            float4 b = __ldg(r1 + i);
            acc[4 * i + 0] += a.x * w0 + b.x * w1;
            acc[4 * i + 1] += a.y * w0 + b.y * w1;
            acc[4 * i + 2] += a.z * w0 + b.z * w1;
            acc[4 * i + 3] += a.w * w0 + b.w * w1;
        }
    }

    // MLP: relu(acc+ba) @ Wb + bb -> relu -> L2norm -> relu -> (@Wn)
    float z[HID];
    #pragma unroll
    for (int k = 0; k < HID; k++) z[k] = fmaxf(acc[k] + sba[k], 0.0f);

    float z2[HID];
    #pragma unroll
    for (int j = 0; j < HID; j++) {
        float a = sbb[j];
        #pragma unroll
        for (int k = 0; k < HID; k++) a += z[k] * sWb[k * HID + j];
        z2[j] = fmaxf(a, 0.0f);
    }

    float ss = 0.0f;
    #pragma unroll
    for (int k = 0; k < HID; k++) ss += z2[k] * z2[k];
    float inv = 1.0f / fmaxf(sqrtf(ss), EPS_NORM);
    #pragma unroll
    for (int k = 0; k < HID; k++) z[k] = fmaxf(z2[k] * inv, 0.0f);   // h

    float o[HID];
    if (mode != 2) {
        #pragma unroll
        for (int j = 0; j < HID; j++) {
            float a = 0.0f;
            #pragma unroll
            for (int k = 0; k < HID; k++) a += z[k] * sWn[k * HID + j];
            o[j] = a;
        }
    } else {
        #pragma unroll
        for (int j = 0; j < HID; j++) o[j] = z[j];
    }

    float4* op = (float4*)(outp + n * HID);
    #pragma unroll
    for (int i = 0; i < 5; i++) {
        float4 v;
        v.x = o[4 * i + 0]; v.y = o[4 * i + 1]; v.z = o[4 * i + 2]; v.w = o[4 * i + 3];
        op[i] = v;
    }
}

// ---------------- pooling ---------------------------------------------------
__global__ void k_zero_pool() {
    int i = blockIdx.x * blockDim.x + threadIdx.x;
    if (i < N_GRAPHS * HID) { g_pmax[i] = 0.0f; g_psum[i] = 0.0f; }
    if (i < N_GRAPHS) g_cnt[i] = 0.0f;
}

__global__ void k_pool(const void* __restrict__ batch_v) {
    int n = blockIdx.x * blockDim.x + threadIdx.x;
    bool valid = n < N_NODES;
    int g = -1;
    if (valid) {
        if (g_is64) g = (int)((const long long*)batch_v)[n];
        else        g = ((const int*)batch_v)[n];
    }
    float v[HID];
    if (valid) {
        const float4* hr = (const float4*)(g_h + (long long)n * HID);
        #pragma unroll
        for (int i = 0; i < 5; i++) {
            float4 t = __ldg(hr + i);
            v[4 * i] = t.x; v[4 * i + 1] = t.y; v[4 * i + 2] = t.z; v[4 * i + 3] = t.w;
        }
    } else {
        #pragma unroll
        for (int k = 0; k < HID; k++) v[k] = 0.0f;
    }

    const unsigned m = 0xffffffffu;
    int g0 = __shfl_sync(m, g, 0);
    bool uni = __all_sync(m, g == g0) && (g0 >= 0);
    int lane = threadIdx.x & 31;

    if (uni) {
        #pragma unroll
        for (int f = 0; f < HID; f++) {
            float s = v[f], mx = v[f];
            #pragma unroll
            for (int off = 16; off > 0; off >>= 1) {
                s += __shfl_xor_sync(m, s, off);
                mx = fmaxf(mx, __shfl_xor_sync(m, mx, off));
            }
            if (lane == 0) {
                atomicAdd(&g_psum[g0 * HID + f], s);
                atomicMax((int*)&g_pmax[g0 * HID + f], __float_as_int(mx));  // h >= 0
            }
        }
        if (lane == 0) atomicAdd(&g_cnt[g0], 32.0f);
    } else if (valid) {
        #pragma unroll
        for (int f = 0; f < HID; f++) {
            atomicAdd(&g_psum[g * HID + f], v[f]);
            atomicMax((int*)&g_pmax[g * HID + f], __float_as_int(v[f]));
        }
        atomicAdd(&g_cnt[g], 1.0f);
    }
}

__global__ void k_final(const float* __restrict__ Wlin, const float* __restrict__ blin,
                        float* __restrict__ out) {
    int idx = blockIdx.x * blockDim.x + threadIdx.x;
    if (idx >= N_GRAPHS * N_CLASSES) return;
    int gph = idx / N_CLASSES, c = idx % N_CLASSES;
    float cnt = g_cnt[gph];
    float icnt = 1.0f / fmaxf(cnt, 1.0f);
    float acc = __ldg(blin + c);
    #pragma unroll
    for (int k = 0; k < HID; k++) {
        float mx = (cnt > 0.0f) ? g_pmax[gph * HID + k] : 0.0f;
        float mean = g_psum[gph * HID + k] * icnt;
        acc += mx * __ldg(Wlin + k * N_CLASSES + c)
             + mean * __ldg(Wlin + (HID + k) * N_CLASSES + c);
    }
    out[idx] = acc;
}

// ---------------- launch ----------------------------------------------------
extern "C" void kernel_launch(void* const* d_in, const int* in_sizes, int n_in,
                              void* d_out, int out_size) {
    const float* x    = (const float*)d_in[0];
    const void*  ei   = d_in[1];
    const void*  batch= d_in[2];
    const float* ew   = (const float*)d_in[3];
    const float* W1a  = (const float*)d_in[4];
    const float* b1a  = (const float*)d_in[5];
    const float* W1b  = (const float*)d_in[6];
    const float* b1b  = (const float*)d_in[7];
    const float* W2a  = (const float*)d_in[8];
    const float* b2a  = (const float*)d_in[9];
    const float* W2b  = (const float*)d_in[10];
    const float* b2b  = (const float*)d_in[11];
    const float* W3a  = (const float*)d_in[12];
    const float* b3a  = (const float*)d_in[13];
    const float* W3b  = (const float*)d_in[14];
    const float* b3b  = (const float*)d_in[15];
    const float* Wlin = (const float*)d_in[16];
    const float* blin = (const float*)d_in[17];
    float* out = (float*)d_out;

    const int eg  = (N_EDGES + 255) / 256;
    const int ng  = (N_NODES + 255) / 256;
    const int mg  = (N_NODES + 127) / 128;
    const int gg  = (N_NODES + GEMM_NPB - 1) / GEMM_NPB;

    k_detect<<<1, 32>>>(ei);

    // CSR build (sorted by dst) + layer-1 input GEMM
    k_zero_deg<<<ng, 256>>>();
    k_hist<<<eg, 256>>>(ei);
    k_gemm_in<<<gg, 256>>>(x, W1a);
    k_scan<<<1, 1024>>>();
    k_fill<<<eg, 256>>>(ei, ew);
    k_pad<<<ng, 256>>>();

    // three fused layers (Wa pre-applied before aggregation)
    k_aggmlp<<<mg, 128>>>(b1a, W1b, b1b, W2a, 0);  // bufA -> bufB (= h1@W2a)
    k_aggmlp<<<mg, 128>>>(b2a, W2b, b2b, W3a, 1);  // bufB -> bufA (= h2@W3a)
    k_aggmlp<<<mg, 128>>>(b3a, W3b, b3b, nullptr, 2);  // bufA -> g_h

    // pooling + classifier
    k_zero_pool<<<3, 1024>>>();
    k_pool<<<ng, 256>>>(batch);
    k_final<<<2, 640>>>(Wlin, blin, out);
}

// round 3
// speedup vs baseline: 1.1165x; 1.1165x over previous
#include <cuda_runtime.h>
#include <cstdint>

#define N_NODES 100000
#define N_EDGES 3200000
#define F_IN 64
#define HID 20
#define N_GRAPHS 128
#define N_CLASSES 10
#define EPS_NORM 1e-12f
#define SCAN_B ((N_NODES + 1023) / 1024)   // 98

// ---------------- scratch (device globals) ---------------------------------
__device__ __align__(16) float g_bufA[N_NODES * HID];
__device__ __align__(16) float g_bufB[N_NODES * HID];
__device__ __align__(16) float g_h[N_NODES * HID];
__device__ __align__(16) int2  g_edge[N_EDGES];      // (src, w bits), grouped by dst
__device__ int g_deg[N_NODES];
__device__ int g_rowptr[N_NODES + 1];
__device__ int g_cursor[N_NODES];
__device__ int g_bsum[128];
__device__ int g_boff[128];
__device__ float g_pmax[N_GRAPHS * HID];
__device__ float g_psum[N_GRAPHS * HID];
__device__ float g_cnt[N_GRAPHS];
__device__ int   g_is64;

// ---------------- dtype probe ----------------------------------------------
__global__ void k_detect(const void* __restrict__ ei) {
    if (threadIdx.x == 0 && blockIdx.x == 0) {
        const long long* p = (const long long*)ei;
        bool ok = true;
        #pragma unroll
        for (int i = 0; i < 16; i++) {
            long long v = p[i];
            if (v < 0 || v >= (long long)N_NODES) ok = false;
        }
        g_is64 = ok ? 1 : 0;
    }
}

// ---------------- CSR build -------------------------------------------------
__global__ void k_zero_deg() {
    int i = blockIdx.x * blockDim.x + threadIdx.x;
    if (i < N_NODES) g_deg[i] = 0;
}

__global__ void k_hist(const void* __restrict__ ei) {
    int e = blockIdx.x * blockDim.x + threadIdx.x;
    if (e >= N_EDGES) return;
    int d;
    if (g_is64) d = (int)((const long long*)ei)[N_EDGES + e];
    else        d = ((const int*)ei)[N_EDGES + e];
    atomicAdd(&g_deg[d], 1);
}

// block sums of deg
__global__ void k_scan1() {
    __shared__ int s[1024];
    int t = threadIdx.x;
    int i = blockIdx.x * 1024 + t;
    s[t] = (i < N_NODES) ? g_deg[i] : 0;
    __syncthreads();
    #pragma unroll
    for (int off = 512; off > 0; off >>= 1) {
        if (t < off) s[t] += s[t + off];
        __syncthreads();
    }
    if (t == 0) g_bsum[blockIdx.x] = s[0];
}

// scan block sums (tiny)
__global__ void k_scan2() {
    if (threadIdx.x == 0) {
        int run = 0;
        for (int i = 0; i < SCAN_B; i++) {
            g_boff[i] = run;
            run += g_bsum[i];
        }
        g_rowptr[N_NODES] = run;
    }
}

// per-block exclusive scan + apply offset
__global__ void k_scan3() {
    __shared__ int s[1024];
    int t = threadIdx.x;
    int i = blockIdx.x * 1024 + t;
    int v = (i < N_NODES) ? g_deg[i] : 0;
    s[t] = v;
    __syncthreads();
    #pragma unroll
    for (int off = 1; off < 1024; off <<= 1) {
        int u = (t >= off) ? s[t - off] : 0;
        __syncthreads();
        s[t] += u;
        __syncthreads();
    }
    if (i < N_NODES) {
        int ex = s[t] - v + g_boff[blockIdx.x];
        g_rowptr[i] = ex;
        g_cursor[i] = ex;
    }
}

__global__ void k_fill(const void* __restrict__ ei, const float* __restrict__ w) {
    int e = blockIdx.x * blockDim.x + threadIdx.x;
    if (e >= N_EDGES) return;
    int s, d;
    if (g_is64) {
        const long long* p = (const long long*)ei;
        s = (int)p[e]; d = (int)p[N_EDGES + e];
    } else {
        const int* p = (const int*)ei;
        s = p[e]; d = p[N_EDGES + e];
    }
    int pos = atomicAdd(&g_cursor[d], 1);
    g_edge[pos] = make_int2(s, __float_as_int(w[e]));
}

// ---------------- layer-1 input GEMM: bufA = x @ W1a ------------------------
#define GB 128
__global__ __launch_bounds__(GB) void k_gemm_in(const float* __restrict__ x,
                                                const float* __restrict__ W) {
    __shared__ float sW[F_IN * HID];          // [k][f], rows 80B -> 16B aligned
    __shared__ float xs[GB][F_IN + 1];        // padded: conflict-free column reads
    int tid = threadIdx.x;
    for (int i = tid; i < F_IN * HID; i += GB) sW[i] = W[i];
    int nbase = blockIdx.x * GB;
    for (int idx = tid; idx < GB * F_IN; idx += GB) {
        int r = idx >> 6, c = idx & 63;
        int gn = nbase + r;
        xs[r][c] = (gn < N_NODES) ? x[(size_t)gn * F_IN + c] : 0.0f;
    }
    __syncthreads();
    int n = nbase + tid;
    if (n >= N_NODES) return;

    float acc[HID];
    #pragma unroll
    for (int j = 0; j < HID; j++) acc[j] = 0.0f;

    #pragma unroll 4
    for (int k = 0; k < F_IN; k++) {
        float xv = xs[tid][k];
        const float4* wr = (const float4*)&sW[k * HID];   // broadcast LDS.128
        #pragma unroll
        for (int q = 0; q < 5; q++) {
            float4 wv = wr[q];
            acc[4 * q + 0] += xv * wv.x;
            acc[4 * q + 1] += xv * wv.y;
            acc[4 * q + 2] += xv * wv.z;
            acc[4 * q + 3] += xv * wv.w;
        }
    }
    float4* op = (float4*)(g_bufA + (size_t)n * HID);
    #pragma unroll
    for (int q = 0; q < 5; q++) {
        float4 v;
        v.x = acc[4 * q]; v.y = acc[4 * q + 1]; v.z = acc[4 * q + 2]; v.w = acc[4 * q + 3];
        op[q] = v;
    }
}

// ---------------- fused gather-aggregate + node MLP (warp per node) --------
// mode: 0 = A->B, 1 = B->A, 2 = A->h
#define AGG_WARPS 8
__global__ __launch_bounds__(AGG_WARPS * 32) void k_aggmlp(
        const float* __restrict__ ba, const float* __restrict__ Wb,
        const float* __restrict__ bb, const float* __restrict__ Wn,
        int mode) {
    __shared__ float sWb[HID * HID], sWn[HID * HID], sba[HID], sbb[HID];
    __shared__ float red[AGG_WARPS][32][HID + 1];
    int tid = threadIdx.x;
    for (int i = tid; i < HID * HID; i += AGG_WARPS * 32) {
        sWb[i] = Wb[i];
        sWn[i] = Wn ? Wn[i] : 0.0f;
    }
    if (tid < HID) { sba[tid] = ba[tid]; sbb[tid] = bb[tid]; }
    __syncthreads();

    int wid = tid >> 5, lane = tid & 31;
    int n = blockIdx.x * AGG_WARPS + wid;
    if (n >= N_NODES) return;

    const float* in = (mode == 1) ? g_bufB : g_bufA;
    float* outp     = (mode == 0) ? g_bufB : ((mode == 1) ? g_bufA : g_h);

    int rs = __ldg(&g_rowptr[n]);
    int re = __ldg(&g_rowptr[n + 1]);

    float acc[HID];
    #pragma unroll
    for (int j = 0; j < HID; j++) acc[j] = 0.0f;

    for (int e = rs + lane; e < re; e += 32) {
        int2 p = __ldg(&g_edge[e]);                 // coalesced 8B
        float w = __int_as_float(p.y);
        const float4* r = (const float4*)(in + (size_t)p.x * HID);
        #pragma unroll
        for (int i = 0; i < 5; i++) {
            float4 a = __ldg(r + i);
            acc[4 * i + 0] += a.x * w;
            acc[4 * i + 1] += a.y * w;
            acc[4 * i + 2] += a.z * w;
            acc[4 * i + 3] += a.w * w;
        }
    }

    // transpose-reduce across lanes: lane j ends with acc_j
    float (*rp)[HID + 1] = red[wid];
    #pragma unroll
    for (int j = 0; j < HID; j++) rp[lane][j] = acc[j];
    __syncwarp();

    const unsigned m = 0xffffffffu;
    int j = lane;
    float aj = 0.0f;
    if (j < HID) {
        #pragma unroll
        for (int l = 0; l < 32; l++) aj += rp[l][j];
    }

    // z_j = relu(a_j + ba_j)
    float zj = (j < HID) ? fmaxf(aj + sba[j], 0.0f) : 0.0f;

    // z2_j = relu(bb_j + sum_k z_k * Wb[k][j])
    float z2j = (j < HID) ? sbb[j] : 0.0f;
    #pragma unroll
    for (int k = 0; k < HID; k++) {
        float zk = __shfl_sync(m, zj, k);
        if (j < HID) z2j += zk * sWb[k * HID + j];
    }
    z2j = fmaxf(z2j, 0.0f);

    // L2 norm over j
    float ss = z2j * z2j;
    #pragma unroll
    for (int off = 16; off > 0; off >>= 1) ss += __shfl_xor_sync(m, ss, off);
    float inv = 1.0f / fmaxf(sqrtf(ss), EPS_NORM);
    float hj = fmaxf(z2j * inv, 0.0f);

    float oj;
    if (mode != 2) {
        oj = 0.0f;
        #pragma unroll
        for (int k = 0; k < HID; k++) {
            float hk = __shfl_sync(m, hj, k);
            if (j < HID) oj += hk * sWn[k * HID + j];
        }
    } else {
        oj = hj;
    }

    if (j < HID) outp[(size_t)n * HID + j] = oj;
}

// ---------------- pooling ---------------------------------------------------
__global__ void k_zero_pool() {
    int i = blockIdx.x * blockDim.x + threadIdx.x;
    if (i < N_GRAPHS * HID) { g_pmax[i] = 0.0f; g_psum[i] = 0.0f; }
    if (i < N_GRAPHS) g_cnt[i] = 0.0f;
}

__global__ void k_pool(const void* __restrict__ batch_v) {
    int n = blockIdx.x * blockDim.x + threadIdx.x;
    bool valid = n < N_NODES;
    int g = -1;
    if (valid) {
        if (g_is64) g = (int)((const long long*)batch_v)[n];
        else        g = ((const int*)batch_v)[n];
    }
    float v[HID];
    if (valid) {
        const float4* hr = (const float4*)(g_h + (size_t)n * HID);
        #pragma unroll
        for (int i = 0; i < 5; i++) {
            float4 t = __ldg(hr + i);
            v[4 * i] = t.x; v[4 * i + 1] = t.y; v[4 * i + 2] = t.z; v[4 * i + 3] = t.w;
        }
    } else {
        #pragma unroll
        for (int k = 0; k < HID; k++) v[k] = 0.0f;
    }

    const unsigned m = 0xffffffffu;
    int g0 = __shfl_sync(m, g, 0);
    bool uni = __all_sync(m, g == g0) && (g0 >= 0);
    int lane = threadIdx.x & 31;

    if (uni) {
        #pragma unroll
        for (int f = 0; f < HID; f++) {
            float s = v[f], mx = v[f];
            #pragma unroll
            for (int off = 16; off > 0; off >>= 1) {
                s += __shfl_xor_sync(m, s, off);
                mx = fmaxf(mx, __shfl_xor_sync(m, mx, off));
            }
            if (lane == 0) {
                atomicAdd(&g_psum[g0 * HID + f], s);
                atomicMax((int*)&g_pmax[g0 * HID + f], __float_as_int(mx));  // h >= 0
            }
        }
        if (lane == 0) atomicAdd(&g_cnt[g0], 32.0f);
    } else if (valid) {
        #pragma unroll
        for (int f = 0; f < HID; f++) {
            atomicAdd(&g_psum[g * HID + f], v[f]);
            atomicMax((int*)&g_pmax[g * HID + f], __float_as_int(v[f]));
        }
        atomicAdd(&g_cnt[g], 1.0f);
    }
}

__global__ void k_final(const float* __restrict__ Wlin, const float* __restrict__ blin,
                        float* __restrict__ out) {
    int idx = blockIdx.x * blockDim.x + threadIdx.x;
    if (idx >= N_GRAPHS * N_CLASSES) return;
    int gph = idx / N_CLASSES, c = idx % N_CLASSES;
    float cnt = g_cnt[gph];
    float icnt = 1.0f / fmaxf(cnt, 1.0f);
    float acc = __ldg(blin + c);
    #pragma unroll
    for (int k = 0; k < HID; k++) {
        float mx = (cnt > 0.0f) ? g_pmax[gph * HID + k] : 0.0f;
        float mean = g_psum[gph * HID + k] * icnt;
        acc += mx * __ldg(Wlin + k * N_CLASSES + c)
             + mean * __ldg(Wlin + (HID + k) * N_CLASSES + c);
    }
    out[idx] = acc;
}

// ---------------- launch ----------------------------------------------------
extern "C" void kernel_launch(void* const* d_in, const int* in_sizes, int n_in,
                              void* d_out, int out_size) {
    const float* x    = (const float*)d_in[0];
    const void*  ei   = d_in[1];
    const void*  batch= d_in[2];
    const float* ew   = (const float*)d_in[3];
    const float* W1a  = (const float*)d_in[4];
    const float* b1a  = (const float*)d_in[5];
    const float* W1b  = (const float*)d_in[6];
    const float* b1b  = (const float*)d_in[7];
    const float* W2a  = (const float*)d_in[8];
    const float* b2a  = (const float*)d_in[9];
    const float* W2b  = (const float*)d_in[10];
    const float* b2b  = (const float*)d_in[11];
    const float* W3a  = (const float*)d_in[12];
    const float* b3a  = (const float*)d_in[13];
    const float* W3b  = (const float*)d_in[14];
    const float* b3b  = (const float*)d_in[15];
    const float* Wlin = (const float*)d_in[16];
    const float* blin = (const float*)d_in[17];
    float* out = (float*)d_out;

    const int eg = (N_EDGES + 255) / 256;
    const int ng = (N_NODES + 255) / 256;
    const int ag = (N_NODES + AGG_WARPS - 1) / AGG_WARPS;
    const int gg = (N_NODES + GB - 1) / GB;

    k_detect<<<1, 32>>>(ei);

    // CSR build (grouped by dst), interleaved with input GEMM
    k_zero_deg<<<ng, 256>>>();
    k_hist<<<eg, 256>>>(ei);
    k_gemm_in<<<gg, GB>>>(x, W1a);
    k_scan1<<<SCAN_B, 1024>>>();
    k_scan2<<<1, 32>>>();
    k_scan3<<<SCAN_B, 1024>>>();
    k_fill<<<eg, 256>>>(ei, ew);

    // three fused layers (each layer's first linear pre-applied before aggregation)
    k_aggmlp<<<ag, AGG_WARPS * 32>>>(b1a, W1b, b1b, W2a, 0);      // bufA -> bufB
    k_aggmlp<<<ag, AGG_WARPS * 32>>>(b2a, W2b, b2b, W3a, 1);      // bufB -> bufA
    k_aggmlp<<<ag, AGG_WARPS * 32>>>(b3a, W3b, b3b, nullptr, 2);  // bufA -> g_h

    // pooling + classifier
    k_zero_pool<<<3, 1024>>>();
    k_pool<<<ng, 256>>>(batch);
    k_final<<<2, 640>>>(Wlin, blin, out);
}

// round 5
// speedup vs baseline: 1.4172x; 1.2693x over previous
#include <cuda_runtime.h>
#include <cstdint>

#define N_NODES 100000
#define N_EDGES 3200000
#define F_IN 64
#define HID 20
#define N_GRAPHS 128
#define N_CLASSES 10
#define EPS_NORM 1e-12f
#define SCAN_B ((N_NODES + 1023) / 1024)   // 98

// ---------------- scratch (device globals) ---------------------------------
__device__ __align__(16) float g_bufA[N_NODES * HID];
__device__ __align__(16) float g_bufB[N_NODES * HID];
__device__ __align__(16) float g_agg[N_NODES * HID];
__device__ __align__(16) float g_h[N_NODES * HID];
__device__ __align__(16) int2  g_edge[N_EDGES];      // (src, w bits), grouped by dst
__device__ int g_deg[N_NODES];
__device__ int g_rowptr[N_NODES + 1];
__device__ int g_cursor[N_NODES];
__device__ int g_bsum[128];
__device__ int g_boff[128];
__device__ float g_pmax[N_GRAPHS * HID];
__device__ float g_psum[N_GRAPHS * HID];
__device__ float g_cnt[N_GRAPHS];
__device__ int   g_is64;

// ---------------- init: dtype probe + zero deg + zero pool ------------------
__global__ void k_init(const void* __restrict__ ei) {
    int i = blockIdx.x * blockDim.x + threadIdx.x;
    if (i == 0) {
        const long long* p = (const long long*)ei;
        bool ok = true;
        #pragma unroll
        for (int q = 0; q < 16; q++) {
            long long v = p[q];
            if (v < 0 || v >= (long long)N_NODES) ok = false;
        }
        g_is64 = ok ? 1 : 0;
    }
    if (i < N_NODES) g_deg[i] = 0;
    if (i < N_GRAPHS * HID) { g_pmax[i] = 0.0f; g_psum[i] = 0.0f; }
    if (i < N_GRAPHS) g_cnt[i] = 0.0f;
}

// ---------------- CSR build -------------------------------------------------
__global__ void k_hist(const void* __restrict__ ei) {
    int e = blockIdx.x * blockDim.x + threadIdx.x;
    if (e >= N_EDGES) return;
    int d;
    if (g_is64) d = (int)((const long long*)ei)[N_EDGES + e];
    else        d = ((const int*)ei)[N_EDGES + e];
    atomicAdd(&g_deg[d], 1);
}

__global__ void k_scan1() {
    __shared__ int s[1024];
    int t = threadIdx.x;
    int i = blockIdx.x * 1024 + t;
    s[t] = (i < N_NODES) ? g_deg[i] : 0;
    __syncthreads();
    #pragma unroll
    for (int off = 512; off > 0; off >>= 1) {
        if (t < off) s[t] += s[t + off];
        __syncthreads();
    }
    if (t == 0) g_bsum[blockIdx.x] = s[0];
}

__global__ void k_scan2() {
    if (threadIdx.x == 0) {
        int run = 0;
        for (int i = 0; i < SCAN_B; i++) {
            g_boff[i] = run;
            run += g_bsum[i];
        }
        g_rowptr[N_NODES] = run;
    }
}

__global__ void k_scan3() {
    __shared__ int s[1024];
    int t = threadIdx.x;
    int i = blockIdx.x * 1024 + t;
    int v = (i < N_NODES) ? g_deg[i] : 0;
    s[t] = v;
    __syncthreads();
    #pragma unroll
    for (int off = 1; off < 1024; off <<= 1) {
        int u = (t >= off) ? s[t - off] : 0;
        __syncthreads();
        s[t] += u;
        __syncthreads();
    }
    if (i < N_NODES) {
        int ex = s[t] - v + g_boff[blockIdx.x];
        g_rowptr[i] = ex;
        g_cursor[i] = ex;
    }
}

__global__ void k_fill(const void* __restrict__ ei, const float* __restrict__ w) {
    int e = blockIdx.x * blockDim.x + threadIdx.x;
    if (e >= N_EDGES) return;
    int s, d;
    if (g_is64) {
        const long long* p = (const long long*)ei;
        s = (int)p[e]; d = (int)p[N_EDGES + e];
    } else {
        const int* p = (const int*)ei;
        s = p[e]; d = p[N_EDGES + e];
    }
    int pos = atomicAdd(&g_cursor[d], 1);
    g_edge[pos] = make_int2(s, __float_as_int(w[e]));
}

// ---------------- layer-1 input GEMM: bufA = x @ W1a ------------------------
// Thread-per-node; x row read directly via float4 LDG (no smem staging).
__global__ __launch_bounds__(256) void k_gemm_in(const float* __restrict__ x,
                                                 const float* __restrict__ W) {
    __shared__ float sW[F_IN * HID];   // 5.1 KB
    int tid = threadIdx.x;
    for (int i = tid; i < F_IN * HID; i += 256) sW[i] = W[i];
    __syncthreads();
    int n = blockIdx.x * 256 + tid;
    if (n >= N_NODES) return;

    const float4* xr = (const float4*)(x + (size_t)n * F_IN);

    float acc[HID];
    #pragma unroll
    for (int j = 0; j < HID; j++) acc[j] = 0.0f;

    #pragma unroll
    for (int c = 0; c < 4; c++) {                 // 4 chunks of 16 features
        float4 xv[4];
        #pragma unroll
        for (int q = 0; q < 4; q++) xv[q] = __ldg(xr + c * 4 + q);
        const float* xs = (const float*)xv;
        #pragma unroll
        for (int kk = 0; kk < 16; kk++) {
            int k = c * 16 + kk;
            float xk = xs[kk];
            const float4* wr = (const float4*)&sW[k * HID];   // broadcast LDS.128
            #pragma unroll
            for (int q = 0; q < 5; q++) {
                float4 wv = wr[q];
                acc[4 * q + 0] += xk * wv.x;
                acc[4 * q + 1] += xk * wv.y;
                acc[4 * q + 2] += xk * wv.z;
                acc[4 * q + 3] += xk * wv.w;
            }
        }
    }
    float4* op = (float4*)(g_bufA + (size_t)n * HID);
    #pragma unroll
    for (int q = 0; q < 5; q++) {
        float4 v;
        v.x = acc[4 * q]; v.y = acc[4 * q + 1]; v.z = acc[4 * q + 2]; v.w = acc[4 * q + 3];
        op[q] = v;
    }
}

// ---------------- aggregation only (warp per node, lean) --------------------
// mode selects input: 0,2 -> bufA ; 1 -> bufB.  Output: g_agg.
#define AW 8
__global__ __launch_bounds__(AW * 32) void k_agg(int mode) {
    __shared__ float red[AW][32][HID + 1];
    int tid = threadIdx.x;
    int wid = tid >> 5, lane = tid & 31;
    int n = blockIdx.x * AW + wid;
    if (n >= N_NODES) return;

    const float* in = (mode == 1) ? g_bufB : g_bufA;
    int rs = __ldg(&g_rowptr[n]);
    int re = __ldg(&g_rowptr[n + 1]);

    float acc[HID];
    #pragma unroll
    for (int j = 0; j < HID; j++) acc[j] = 0.0f;

    for (int e = rs + lane; e < re; e += 32) {
        int2 p = __ldg(&g_edge[e]);
        float w = __int_as_float(p.y);
        const float4* r = (const float4*)(in + (size_t)p.x * HID);
        #pragma unroll
        for (int i = 0; i < 5; i++) {
            float4 a = __ldg(r + i);
            acc[4 * i + 0] += a.x * w;
            acc[4 * i + 1] += a.y * w;
            acc[4 * i + 2] += a.z * w;
            acc[4 * i + 3] += a.w * w;
        }
    }

    float (*rp)[HID + 1] = red[wid];
    #pragma unroll
    for (int j = 0; j < HID; j++) rp[lane][j] = acc[j];
    __syncwarp();

    if (lane < HID) {
        float s = 0.0f;
        #pragma unroll
        for (int l = 0; l < 32; l++) s += rp[l][lane];
        g_agg[(size_t)n * HID + lane] = s;      // coalesced 80B per warp
    }
}

// ---------------- node MLP (thread per node): g_agg -> out ------------------
// mode: 0 -> bufB, 1 -> bufA, 2 -> g_h (no Wn)
__global__ __launch_bounds__(128) void k_mlp(const float* __restrict__ ba,
                                             const float* __restrict__ Wb,
                                             const float* __restrict__ bb,
                                             const float* __restrict__ Wn,
                                             int mode) {
    __shared__ float sWb[HID * HID], sWn[HID * HID], sba[HID], sbb[HID];
    int tid = threadIdx.x;
    for (int i = tid; i < HID * HID; i += 128) {
        sWb[i] = Wb[i];
        sWn[i] = Wn ? Wn[i] : 0.0f;
    }
    if (tid < HID) { sba[tid] = ba[tid]; sbb[tid] = bb[tid]; }
    __syncthreads();
    int n = blockIdx.x * 128 + tid;
    if (n >= N_NODES) return;

    float4 t[5];
    const float4* ag = (const float4*)(g_agg + (size_t)n * HID);
    #pragma unroll
    for (int i = 0; i < 5; i++) t[i] = __ldg(ag + i);
    float* zt = (float*)t;

    float z[HID];
    #pragma unroll
    for (int k = 0; k < HID; k++) z[k] = fmaxf(zt[k] + sba[k], 0.0f);

    float z2[HID];
    #pragma unroll
    for (int j = 0; j < HID; j++) {
        float a = sbb[j];
        #pragma unroll
        for (int k = 0; k < HID; k++) a += z[k] * sWb[k * HID + j];
        z2[j] = fmaxf(a, 0.0f);
    }

    float ss = 0.0f;
    #pragma unroll
    for (int k = 0; k < HID; k++) ss += z2[k] * z2[k];
    float inv = 1.0f / fmaxf(sqrtf(ss), EPS_NORM);
    #pragma unroll
    for (int k = 0; k < HID; k++) z[k] = fmaxf(z2[k] * inv, 0.0f);  // h

    float o[HID];
    if (mode != 2) {
        #pragma unroll
        for (int j = 0; j < HID; j++) {
            float a = 0.0f;
            #pragma unroll
            for (int k = 0; k < HID; k++) a += z[k] * sWn[k * HID + j];
            o[j] = a;
        }
    } else {
        #pragma unroll
        for (int j = 0; j < HID; j++) o[j] = z[j];
    }

    float* outp = (mode == 0) ? g_bufB : ((mode == 1) ? g_bufA : g_h);
    float4* op = (float4*)(outp + (size_t)n * HID);
    #pragma unroll
    for (int i = 0; i < 5; i++) {
        float4 v;
        v.x = o[4 * i + 0]; v.y = o[4 * i + 1]; v.z = o[4 * i + 2]; v.w = o[4 * i + 3];
        op[i] = v;
    }
}

// ---------------- pooling ---------------------------------------------------
__global__ void k_pool(const void* __restrict__ batch_v) {
    int n = blockIdx.x * blockDim.x + threadIdx.x;
    bool valid = n < N_NODES;
    int g = -1;
    if (valid) {
        if (g_is64) g = (int)((const long long*)batch_v)[n];
        else        g = ((const int*)batch_v)[n];
    }
    float v[HID];
    if (valid) {
        const float4* hr = (const float4*)(g_h + (size_t)n * HID);
        #pragma unroll
        for (int i = 0; i < 5; i++) {
            float4 t = __ldg(hr + i);
            v[4 * i] = t.x; v[4 * i + 1] = t.y; v[4 * i + 2] = t.z; v[4 * i + 3] = t.w;
        }
    } else {
        #pragma unroll
        for (int k = 0; k < HID; k++) v[k] = 0.0f;
    }

    const unsigned m = 0xffffffffu;
    int g0 = __shfl_sync(m, g, 0);
    bool uni = __all_sync(m, g == g0) && (g0 >= 0);
    int lane = threadIdx.x & 31;

    if (uni) {
        #pragma unroll
        for (int f = 0; f < HID; f++) {
            float s = v[f], mx = v[f];
            #pragma unroll
            for (int off = 16; off > 0; off >>= 1) {
                s += __shfl_xor_sync(m, s, off);
                mx = fmaxf(mx, __shfl_xor_sync(m, mx, off));
            }
            if (lane == 0) {
                atomicAdd(&g_psum[g0 * HID + f], s);
                atomicMax((int*)&g_pmax[g0 * HID + f], __float_as_int(mx));  // h >= 0
            }
        }
        if (lane == 0) atomicAdd(&g_cnt[g0], 32.0f);
    } else if (valid) {
        #pragma unroll
        for (int f = 0; f < HID; f++) {
            atomicAdd(&g_psum[g * HID + f], v[f]);
            atomicMax((int*)&g_pmax[g * HID + f], __float_as_int(v[f]));
        }
        atomicAdd(&g_cnt[g], 1.0f);
    }
}

__global__ void k_final(const float* __restrict__ Wlin, const float* __restrict__ blin,
                        float* __restrict__ out) {
    int idx = blockIdx.x * blockDim.x + threadIdx.x;
    if (idx >= N_GRAPHS * N_CLASSES) return;
    int gph = idx / N_CLASSES, c = idx % N_CLASSES;
    float cnt = g_cnt[gph];
    float icnt = 1.0f / fmaxf(cnt, 1.0f);
    float acc = __ldg(blin + c);
    #pragma unroll
    for (int k = 0; k < HID; k++) {
        float mx = (cnt > 0.0f) ? g_pmax[gph * HID + k] : 0.0f;
        float mean = g_psum[gph * HID + k] * icnt;
        acc += mx * __ldg(Wlin + k * N_CLASSES + c)
             + mean * __ldg(Wlin + (HID + k) * N_CLASSES + c);
    }
    out[idx] = acc;
}

// ---------------- launch ----------------------------------------------------
extern "C" void kernel_launch(void* const* d_in, const int* in_sizes, int n_in,
                              void* d_out, int out_size) {
    const float* x    = (const float*)d_in[0];
    const void*  ei   = d_in[1];
    const void*  batch= d_in[2];
    const float* ew   = (const float*)d_in[3];
    const float* W1a  = (const float*)d_in[4];
    const float* b1a  = (const float*)d_in[5];
    const float* W1b  = (const float*)d_in[6];
    const float* b1b  = (const float*)d_in[7];
    const float* W2a  = (const float*)d_in[8];
    const float* b2a  = (const float*)d_in[9];
    const float* W2b  = (const float*)d_in[10];
    const float* b2b  = (const float*)d_in[11];
    const float* W3a  = (const float*)d_in[12];
    const float* b3a  = (const float*)d_in[13];
    const float* W3b  = (const float*)d_in[14];
    const float* b3b  = (const float*)d_in[15];
    const float* Wlin = (const float*)d_in[16];
    const float* blin = (const float*)d_in[17];
    float* out = (float*)d_out;

    const int eg = (N_EDGES + 255) / 256;
    const int ng = (N_NODES + 255) / 256;
    const int ag = (N_NODES + AW - 1) / AW;
    const int mg = (N_NODES + 127) / 128;
    const int gg = (N_NODES + 255) / 256;

    k_init<<<ng, 256>>>(ei);
    k_hist<<<eg, 256>>>(ei);
    k_gemm_in<<<gg, 256>>>(x, W1a);
    k_scan1<<<SCAN_B, 1024>>>();
    k_scan2<<<1, 32>>>();
    k_scan3<<<SCAN_B, 1024>>>();
    k_fill<<<eg, 256>>>(ei, ew);

    // three layers: agg (gather) + node MLP  (Wa pre-applied before aggregation)
    k_agg<<<ag, AW * 32>>>(0);  k_mlp<<<mg, 128>>>(b1a, W1b, b1b, W2a, 0);     // -> bufB
    k_agg<<<ag, AW * 32>>>(1);  k_mlp<<<mg, 128>>>(b2a, W2b, b2b, W3a, 1);     // -> bufA
    k_agg<<<ag, AW * 32>>>(2);  k_mlp<<<mg, 128>>>(b3a, W3b, b3b, nullptr, 2); // -> g_h

    k_pool<<<ng, 256>>>(batch);
    k_final<<<2, 640>>>(Wlin, blin, out);
}

// round 8
// speedup vs baseline: 1.5528x; 1.0957x over previous
#include <cuda_runtime.h>
#include <cuda_fp16.h>
#include <cstdint>

#define N_NODES 100000
#define N_EDGES 3200000
#define F_IN 64
#define HID 20
#define H2  (HID / 2)                       // 10 half2 per row (40B)
#define N_GRAPHS 128
#define N_CLASSES 10
#define EPS_NORM 1e-12f
#define SCAN_B ((N_NODES + 1023) / 1024)    // 98

// ---------------- scratch (device globals) ---------------------------------
__device__ __align__(16) __half2 g_bufA[N_NODES * H2];   // fp16 features (40B rows)
__device__ __align__(16) __half2 g_bufB[N_NODES * H2];
__device__ __align__(16) float g_agg[N_NODES * HID];
__device__ __align__(16) float g_h[N_NODES * HID];
__device__ __align__(16) int2  g_edge[N_EDGES];          // (src, w bits), grouped by dst
__device__ int g_deg[N_NODES];
__device__ int g_rowptr[N_NODES + 1];
__device__ int g_cursor[N_NODES];
__device__ int g_bsum[128];
__device__ int g_boff[128];
__device__ float g_pmax[N_GRAPHS * HID];
__device__ float g_psum[N_GRAPHS * HID];
__device__ float g_cnt[N_GRAPHS];
__device__ int   g_is64;

// ---------------- init: dtype probe + zero deg + zero pool ------------------
__global__ void k_init(const void* __restrict__ ei) {
    int i = blockIdx.x * blockDim.x + threadIdx.x;
    if (i == 0) {
        const long long* p = (const long long*)ei;
        bool ok = true;
        #pragma unroll
        for (int q = 0; q < 16; q++) {
            long long v = p[q];
            if (v < 0 || v >= (long long)N_NODES) ok = false;
        }
        g_is64 = ok ? 1 : 0;
    }
    if (i < N_NODES) g_deg[i] = 0;
    if (i < N_GRAPHS * HID) { g_pmax[i] = 0.0f; g_psum[i] = 0.0f; }
    if (i < N_GRAPHS) g_cnt[i] = 0.0f;
}

// ---------------- CSR build -------------------------------------------------
__global__ void k_hist(const void* __restrict__ ei) {
    int e = blockIdx.x * blockDim.x + threadIdx.x;
    if (e >= N_EDGES) return;
    int d;
    if (g_is64) d = (int)((const long long*)ei)[N_EDGES + e];
    else        d = ((const int*)ei)[N_EDGES + e];
    atomicAdd(&g_deg[d], 1);
}

__global__ void k_scan1() {
    __shared__ int s[1024];
    int t = threadIdx.x;
    int i = blockIdx.x * 1024 + t;
    s[t] = (i < N_NODES) ? g_deg[i] : 0;
    __syncthreads();
    #pragma unroll
    for (int off = 512; off > 0; off >>= 1) {
        if (t < off) s[t] += s[t + off];
        __syncthreads();
    }
    if (t == 0) g_bsum[blockIdx.x] = s[0];
}

__global__ void k_scan2() {
    if (threadIdx.x == 0) {
        int run = 0;
        for (int i = 0; i < SCAN_B; i++) {
            g_boff[i] = run;
            run += g_bsum[i];
        }
        g_rowptr[N_NODES] = run;
    }
}

__global__ void k_scan3() {
    __shared__ int s[1024];
    int t = threadIdx.x;
    int i = blockIdx.x * 1024 + t;
    int v = (i < N_NODES) ? g_deg[i] : 0;
    s[t] = v;
    __syncthreads();
    #pragma unroll
    for (int off = 1; off < 1024; off <<= 1) {
        int u = (t >= off) ? s[t - off] : 0;
        __syncthreads();
        s[t] += u;
        __syncthreads();
    }
    if (i < N_NODES) {
        int ex = s[t] - v + g_boff[blockIdx.x];
        g_rowptr[i] = ex;
        g_cursor[i] = ex;
    }
}

__global__ void k_fill(const void* __restrict__ ei, const float* __restrict__ w) {
    int e = blockIdx.x * blockDim.x + threadIdx.x;
    if (e >= N_EDGES) return;
    int s, d;
    if (g_is64) {
        const long long* p = (const long long*)ei;
        s = (int)p[e]; d = (int)p[N_EDGES + e];
    } else {
        const int* p = (const int*)ei;
        s = p[e]; d = p[N_EDGES + e];
    }
    int pos = atomicAdd(&g_cursor[d], 1);
    g_edge[pos] = make_int2(s, __float_as_int(w[e]));
}

// ---------------- helpers ---------------------------------------------------
__device__ __forceinline__ void store_row_fp16(__half2* base, int n, const float* o) {
    // pack 20 floats -> 10 half2 -> 5 x 8B stores (row base 40B => 8B aligned)
    uint2* op = (uint2*)(base + (size_t)n * H2);
    #pragma unroll
    for (int q = 0; q < 5; q++) {
        __half2 a = __floats2half2_rn(o[4 * q + 0], o[4 * q + 1]);
        __half2 b = __floats2half2_rn(o[4 * q + 2], o[4 * q + 3]);
        uint2 u;
        u.x = *(unsigned*)&a;
        u.y = *(unsigned*)&b;
        op[q] = u;
    }
}

// ---------------- layer-1 input GEMM: bufA = fp16(x @ W1a) ------------------
__global__ __launch_bounds__(256) void k_gemm_in(const float* __restrict__ x,
                                                 const float* __restrict__ W) {
    __shared__ float sW[F_IN * HID];   // 5.1 KB
    int tid = threadIdx.x;
    for (int i = tid; i < F_IN * HID; i += 256) sW[i] = W[i];
    __syncthreads();
    int n = blockIdx.x * 256 + tid;
    if (n >= N_NODES) return;

    const float4* xr = (const float4*)(x + (size_t)n * F_IN);

    float acc[HID];
    #pragma unroll
    for (int j = 0; j < HID; j++) acc[j] = 0.0f;

    #pragma unroll
    for (int c = 0; c < 4; c++) {
        float4 xv[4];
        #pragma unroll
        for (int q = 0; q < 4; q++) xv[q] = __ldg(xr + c * 4 + q);
        const float* xs = (const float*)xv;
        #pragma unroll
        for (int kk = 0; kk < 16; kk++) {
            int k = c * 16 + kk;
            float xk = xs[kk];
            const float4* wr = (const float4*)&sW[k * HID];
            #pragma unroll
            for (int q = 0; q < 5; q++) {
                float4 wv = wr[q];
                acc[4 * q + 0] += xk * wv.x;
                acc[4 * q + 1] += xk * wv.y;
                acc[4 * q + 2] += xk * wv.z;
                acc[4 * q + 3] += xk * wv.w;
            }
        }
    }
    store_row_fp16(g_bufA, n, acc);
}

// ---------------- aggregation (warp per node, fp16 gather, fp32 accum) ------
// mode selects input: 0,2 -> bufA ; 1 -> bufB.  Output: g_agg (fp32).
#define AW 8
__global__ __launch_bounds__(AW * 32) void k_agg(int mode) {
    __shared__ float red[AW][32][HID + 1];
    int tid = threadIdx.x;
    int wid = tid >> 5, lane = tid & 31;
    int n = blockIdx.x * AW + wid;
    if (n >= N_NODES) return;

    const __half2* in = (mode == 1) ? g_bufB : g_bufA;
    int rs = __ldg(&g_rowptr[n]);
    int re = __ldg(&g_rowptr[n + 1]);

    float acc[HID];
    #pragma unroll
    for (int j = 0; j < HID; j++) acc[j] = 0.0f;

    for (int e = rs + lane; e < re; e += 32) {
        int2 p = __ldg(&g_edge[e]);
        float w = __int_as_float(p.y);
        const uint2* r = (const uint2*)(in + (size_t)p.x * H2);  // 40B row, 8B aligned
        #pragma unroll
        for (int i = 0; i < 5; i++) {
            uint2 u = __ldg(r + i);
            __half2 h0 = *(__half2*)&u.x;
            __half2 h1 = *(__half2*)&u.y;
            float2 f0 = __half22float2(h0);
            float2 f1 = __half22float2(h1);
            acc[4 * i + 0] += f0.x * w;
            acc[4 * i + 1] += f0.y * w;
            acc[4 * i + 2] += f1.x * w;
            acc[4 * i + 3] += f1.y * w;
        }
    }

    float (*rp)[HID + 1] = red[wid];
    #pragma unroll
    for (int j = 0; j < HID; j++) rp[lane][j] = acc[j];
    __syncwarp();

    if (lane < HID) {
        float s = 0.0f;
        #pragma unroll
        for (int l = 0; l < 32; l++) s += rp[l][lane];
        g_agg[(size_t)n * HID + lane] = s;      // coalesced 80B per warp
    }
}

// ---------------- node MLP (thread per node): g_agg -> out ------------------
// mode: 0 -> bufB(fp16), 1 -> bufA(fp16), 2 -> g_h(fp32)
__global__ __launch_bounds__(128) void k_mlp(const float* __restrict__ ba,
                                             const float* __restrict__ Wb,
                                             const float* __restrict__ bb,
                                             const float* __restrict__ Wn,
                                             int mode) {
    __shared__ float sWb[HID * HID], sWn[HID * HID], sba[HID], sbb[HID];
    int tid = threadIdx.x;
    for (int i = tid; i < HID * HID; i += 128) {
        sWb[i] = Wb[i];
        sWn[i] = Wn ? Wn[i] : 0.0f;
    }
    if (tid < HID) { sba[tid] = ba[tid]; sbb[tid] = bb[tid]; }
    __syncthreads();
    int n = blockIdx.x * 128 + tid;
    if (n >= N_NODES) return;

    float4 t[5];
    const float4* ag = (const float4*)(g_agg + (size_t)n * HID);
    #pragma unroll
    for (int i = 0; i < 5; i++) t[i] = __ldg(ag + i);
    float* zt = (float*)t;

    float z[HID];
    #pragma unroll
    for (int k = 0; k < HID; k++) z[k] = fmaxf(zt[k] + sba[k], 0.0f);

    float z2[HID];
    #pragma unroll
    for (int j = 0; j < HID; j++) {
        float a = sbb[j];
        #pragma unroll
        for (int k = 0; k < HID; k++) a += z[k] * sWb[k * HID + j];
        z2[j] = fmaxf(a, 0.0f);
    }

    float ss = 0.0f;
    #pragma unroll
    for (int k = 0; k < HID; k++) ss += z2[k] * z2[k];
    float inv = 1.0f / fmaxf(sqrtf(ss), EPS_NORM);
    #pragma unroll
    for (int k = 0; k < HID; k++) z[k] = fmaxf(z2[k] * inv, 0.0f);  // h

    float o[HID];
    if (mode != 2) {
        #pragma unroll
        for (int j = 0; j < HID; j++) {
            float a = 0.0f;
            #pragma unroll
            for (int k = 0; k < HID; k++) a += z[k] * sWn[k * HID + j];
            o[j] = a;
        }
        store_row_fp16((mode == 0) ? g_bufB : g_bufA, n, o);
    } else {
        float4* op = (float4*)(g_h + (size_t)n * HID);
        #pragma unroll
        for (int i = 0; i < 5; i++) {
            float4 v;
            v.x = z[4 * i + 0]; v.y = z[4 * i + 1]; v.z = z[4 * i + 2]; v.w = z[4 * i + 3];
            op[i] = v;
        }
    }
}

// ---------------- pooling ---------------------------------------------------
__global__ void k_pool(const void* __restrict__ batch_v) {
    int n = blockIdx.x * blockDim.x + threadIdx.x;
    bool valid = n < N_NODES;
    int g = -1;
    if (valid) {
        if (g_is64) g = (int)((const long long*)batch_v)[n];
        else        g = ((const int*)batch_v)[n];
    }
    float v[HID];
    if (valid) {
        const float4* hr = (const float4*)(g_h + (size_t)n * HID);
        #pragma unroll
        for (int i = 0; i < 5; i++) {
            float4 t = __ldg(hr + i);
            v[4 * i] = t.x; v[4 * i + 1] = t.y; v[4 * i + 2] = t.z; v[4 * i + 3] = t.w;
        }
    } else {
        #pragma unroll
        for (int k = 0; k < HID; k++) v[k] = 0.0f;
    }

    const unsigned m = 0xffffffffu;
    int g0 = __shfl_sync(m, g, 0);
    bool uni = __all_sync(m, g == g0) && (g0 >= 0);
    int lane = threadIdx.x & 31;

    if (uni) {
        #pragma unroll
        for (int f = 0; f < HID; f++) {
            float s = v[f], mx = v[f];
            #pragma unroll
            for (int off = 16; off > 0; off >>= 1) {
                s += __shfl_xor_sync(m, s, off);
                mx = fmaxf(mx, __shfl_xor_sync(m, mx, off));
            }
            if (lane == 0) {
                atomicAdd(&g_psum[g0 * HID + f], s);
                atomicMax((int*)&g_pmax[g0 * HID + f], __float_as_int(mx));  // h >= 0
            }
        }
        if (lane == 0) atomicAdd(&g_cnt[g0], 32.0f);
    } else if (valid) {
        #pragma unroll
        for (int f = 0; f < HID; f++) {
            atomicAdd(&g_psum[g * HID + f], v[f]);
            atomicMax((int*)&g_pmax[g * HID + f], __float_as_int(v[f]));
        }
        atomicAdd(&g_cnt[g], 1.0f);
    }
}

__global__ void k_final(const float* __restrict__ Wlin, const float* __restrict__ blin,
                        float* __restrict__ out) {
    int idx = blockIdx.x * blockDim.x + threadIdx.x;
    if (idx >= N_GRAPHS * N_CLASSES) return;
    int gph = idx / N_CLASSES, c = idx % N_CLASSES;
    float cnt = g_cnt[gph];
    float icnt = 1.0f / fmaxf(cnt, 1.0f);
    float acc = __ldg(blin + c);
    #pragma unroll
    for (int k = 0; k < HID; k++) {
        float mx = (cnt > 0.0f) ? g_pmax[gph * HID + k] : 0.0f;
        float mean = g_psum[gph * HID + k] * icnt;
        acc += mx * __ldg(Wlin + k * N_CLASSES + c)
             + mean * __ldg(Wlin + (HID + k) * N_CLASSES + c);
    }
    out[idx] = acc;
}

// ---------------- launch ----------------------------------------------------
extern "C" void kernel_launch(void* const* d_in, const int* in_sizes, int n_in,
                              void* d_out, int out_size) {
    const float* x    = (const float*)d_in[0];
    const void*  ei   = d_in[1];
    const void*  batch= d_in[2];
    const float* ew   = (const float*)d_in[3];
    const float* W1a  = (const float*)d_in[4];
    const float* b1a  = (const float*)d_in[5];
    const float* W1b  = (const float*)d_in[6];
    const float* b1b  = (const float*)d_in[7];
    const float* W2a  = (const float*)d_in[8];
    const float* b2a  = (const float*)d_in[9];
    const float* W2b  = (const float*)d_in[10];
    const float* b2b  = (const float*)d_in[11];
    const float* W3a  = (const float*)d_in[12];
    const float* b3a  = (const float*)d_in[13];
    const float* W3b  = (const float*)d_in[14];
    const float* b3b  = (const float*)d_in[15];
    const float* Wlin = (const float*)d_in[16];
    const float* blin = (const float*)d_in[17];
    float* out = (float*)d_out;

    const int eg = (N_EDGES + 255) / 256;
    const int ng = (N_NODES + 255) / 256;
    const int ag = (N_NODES + AW - 1) / AW;
    const int mg = (N_NODES + 127) / 128;
    const int gg = (N_NODES + 255) / 256;

    k_init<<<ng, 256>>>(ei);
    k_hist<<<eg, 256>>>(ei);
    k_gemm_in<<<gg, 256>>>(x, W1a);
    k_scan1<<<SCAN_B, 1024>>>();
    k_scan2<<<1, 32>>>();
    k_scan3<<<SCAN_B, 1024>>>();
    k_fill<<<eg, 256>>>(ei, ew);

    // three layers: agg (fp16 gather) + node MLP (fp32)
    k_agg<<<ag, AW * 32>>>(0);  k_mlp<<<mg, 128>>>(b1a, W1b, b1b, W2a, 0);     // -> bufB
    k_agg<<<ag, AW * 32>>>(1);  k_mlp<<<mg, 128>>>(b2a, W2b, b2b, W3a, 1);     // -> bufA
    k_agg<<<ag, AW * 32>>>(2);  k_mlp<<<mg, 128>>>(b3a, W3b, b3b, nullptr, 2); // -> g_h

    k_pool<<<ng, 256>>>(batch);
    k_final<<<2, 640>>>(Wlin, blin, out);
}

// round 10
// speedup vs baseline: 1.6447x; 1.0592x over previous
#include <cuda_runtime.h>
#include <cuda_fp16.h>
#include <cstdint>

#define N_NODES 100000
#define N_EDGES 3200000
#define F_IN 64
#define HID 20
#define H2P 12                              // half2 per padded row (48B)
#define N_GRAPHS 128
#define N_CLASSES 10
#define EPS_NORM 1e-12f
#define SCAN_B ((N_NODES + 1023) / 1024)    // 98

// ---------------- scratch (device globals) ---------------------------------
__device__ __align__(16) __half2 g_bufA[N_NODES * H2P];  // fp16 rows padded to 48B
__device__ __align__(16) __half2 g_bufB[N_NODES * H2P];
__device__ __align__(16) float g_agg[N_NODES * HID];
__device__ __align__(16) int g_edge_raw[2 * N_EDGES];    // int2 (s,w) or int (s) per edge
__device__ int g_deg[N_NODES];
__device__ int g_rowptr[N_NODES + 1];
__device__ int g_cursor[N_NODES];
__device__ int g_bsum[128];
__device__ int g_boff[128];
__device__ float g_pmax[N_GRAPHS * HID];
__device__ float g_psum[N_GRAPHS * HID];
__device__ float g_cnt[N_GRAPHS];
__device__ int   g_is64;
__device__ int   g_wuni;                                 // 1 if all edge weights == 1.0f

// ---------------- init: dtype probe + zero deg + zero pool ------------------
__global__ void k_init(const void* __restrict__ ei) {
    int i = blockIdx.x * blockDim.x + threadIdx.x;
    if (i == 0) {
        const long long* p = (const long long*)ei;
        bool ok = true;
        #pragma unroll
        for (int q = 0; q < 16; q++) {
            long long v = p[q];
            if (v < 0 || v >= (long long)N_NODES) ok = false;
        }
        g_is64 = ok ? 1 : 0;
        g_wuni = 1;
    }
    if (i < N_NODES) g_deg[i] = 0;
    if (i < N_GRAPHS * HID) { g_pmax[i] = 0.0f; g_psum[i] = 0.0f; }
    if (i < N_GRAPHS) g_cnt[i] = 0.0f;
}

// ---------------- CSR build -------------------------------------------------
__global__ void k_hist(const void* __restrict__ ei, const float* __restrict__ w) {
    int e = blockIdx.x * blockDim.x + threadIdx.x;
    if (e >= N_EDGES) return;
    int d;
    if (g_is64) d = (int)((const long long*)ei)[N_EDGES + e];
    else        d = ((const int*)ei)[N_EDGES + e];
    atomicAdd(&g_deg[d], 1);
    if (w[e] != 1.0f) g_wuni = 0;   // benign race: all writers store 0
}

__global__ void k_scan1() {
    __shared__ int s[1024];
    int t = threadIdx.x;
    int i = blockIdx.x * 1024 + t;
    s[t] = (i < N_NODES) ? g_deg[i] : 0;
    __syncthreads();
    #pragma unroll
    for (int off = 512; off > 0; off >>= 1) {
        if (t < off) s[t] += s[t + off];
        __syncthreads();
    }
    if (t == 0) g_bsum[blockIdx.x] = s[0];
}

__global__ void k_scan2() {
    if (threadIdx.x == 0) {
        int run = 0;
        for (int i = 0; i < SCAN_B; i++) {
            g_boff[i] = run;
            run += g_bsum[i];
        }
        g_rowptr[N_NODES] = run;
    }
}

__global__ void k_scan3() {
    __shared__ int s[1024];
    int t = threadIdx.x;
    int i = blockIdx.x * 1024 + t;
    int v = (i < N_NODES) ? g_deg[i] : 0;
    s[t] = v;
    __syncthreads();
    #pragma unroll
    for (int off = 1; off < 1024; off <<= 1) {
        int u = (t >= off) ? s[t - off] : 0;
        __syncthreads();
        s[t] += u;
        __syncthreads();
    }
    if (i < N_NODES) {
        int ex = s[t] - v + g_boff[blockIdx.x];
        g_rowptr[i] = ex;
        g_cursor[i] = ex;
    }
}

__global__ void k_fill(const void* __restrict__ ei, const float* __restrict__ w) {
    int e = blockIdx.x * blockDim.x + threadIdx.x;
    if (e >= N_EDGES) return;
    int s, d;
    if (g_is64) {
        const long long* p = (const long long*)ei;
        s = (int)p[e]; d = (int)p[N_EDGES + e];
    } else {
        const int* p = (const int*)ei;
        s = p[e]; d = p[N_EDGES + e];
    }
    int pos = atomicAdd(&g_cursor[d], 1);
    if (g_wuni) {
        g_edge_raw[pos] = s;                          // src only, 4B
    } else {
        ((int2*)g_edge_raw)[pos] = make_int2(s, __float_as_int(w[e]));
    }
}

// ---------------- helpers ---------------------------------------------------
__device__ __forceinline__ void store_row_fp16(__half2* base, int n, const float* o) {
    // 20 floats -> 10 half2 + 2 zero half2 padding -> 3 x 16B stores (48B row)
    uint4* op = (uint4*)(base + (size_t)n * H2P);
    unsigned hp[12];
    #pragma unroll
    for (int q = 0; q < 10; q++) {
        __half2 h = __floats2half2_rn(o[2 * q], o[2 * q + 1]);
        hp[q] = *(unsigned*)&h;
    }
    hp[10] = 0u; hp[11] = 0u;
    op[0] = make_uint4(hp[0], hp[1], hp[2], hp[3]);
    op[1] = make_uint4(hp[4], hp[5], hp[6], hp[7]);
    op[2] = make_uint4(hp[8], hp[9], hp[10], hp[11]);
}

__device__ __forceinline__ void accum_row(const __half2* in, int src, float w,
                                          bool uni, float* acc) {
    const uint4* r = (const uint4*)(in + (size_t)src * H2P);   // 48B row, 16B aligned
    uint4 a = __ldg(r);
    uint4 b = __ldg(r + 1);
    uint2 c = __ldg((const uint2*)(r + 2));
    unsigned hp[10] = {a.x, a.y, a.z, a.w, b.x, b.y, b.z, b.w, c.x, c.y};
    if (uni) {
        #pragma unroll
        for (int q = 0; q < 10; q++) {
            float2 f = __half22float2(*(__half2*)&hp[q]);
            acc[2 * q + 0] += f.x;
            acc[2 * q + 1] += f.y;
        }
    } else {
        #pragma unroll
        for (int q = 0; q < 10; q++) {
            float2 f = __half22float2(*(__half2*)&hp[q]);
            acc[2 * q + 0] += f.x * w;
            acc[2 * q + 1] += f.y * w;
        }
    }
}

// ---------------- layer-1 input GEMM: bufA = fp16(x @ W1a) ------------------
__global__ __launch_bounds__(256) void k_gemm_in(const float* __restrict__ x,
                                                 const float* __restrict__ W) {
    __shared__ float sW[F_IN * HID];   // 5.1 KB
    int tid = threadIdx.x;
    for (int i = tid; i < F_IN * HID; i += 256) sW[i] = W[i];
    __syncthreads();
    int n = blockIdx.x * 256 + tid;
    if (n >= N_NODES) return;

    const float4* xr = (const float4*)(x + (size_t)n * F_IN);

    float acc[HID];
    #pragma unroll
    for (int j = 0; j < HID; j++) acc[j] = 0.0f;

    #pragma unroll
    for (int c = 0; c < 4; c++) {
        float4 xv[4];
        #pragma unroll
        for (int q = 0; q < 4; q++) xv[q] = __ldg(xr + c * 4 + q);
        const float* xs = (const float*)xv;
        #pragma unroll
        for (int kk = 0; kk < 16; kk++) {
            int k = c * 16 + kk;
            float xk = xs[kk];
            const float4* wr = (const float4*)&sW[k * HID];
            #pragma unroll
            for (int q = 0; q < 5; q++) {
                float4 wv = wr[q];
                acc[4 * q + 0] += xk * wv.x;
                acc[4 * q + 1] += xk * wv.y;
                acc[4 * q + 2] += xk * wv.z;
                acc[4 * q + 3] += xk * wv.w;
            }
        }
    }
    store_row_fp16(g_bufA, n, acc);
}

// ---------------- aggregation (warp per node, 3 loads/edge) -----------------
// mode selects input: 0,2 -> bufA ; 1 -> bufB.  Output: g_agg (fp32).
#define AW 8
__global__ __launch_bounds__(AW * 32) void k_agg(int mode) {
    __shared__ float red[AW][32][HID + 1];
    int tid = threadIdx.x;
    int wid = tid >> 5, lane = tid & 31;
    int n = blockIdx.x * AW + wid;
    if (n >= N_NODES) return;

    const __half2* in = (mode == 1) ? g_bufB : g_bufA;
    bool uni = (g_wuni != 0);
    int rs = __ldg(&g_rowptr[n]);
    int re = __ldg(&g_rowptr[n + 1]);

    float acc[HID];
    #pragma unroll
    for (int j = 0; j < HID; j++) acc[j] = 0.0f;

    if (uni) {
        const int* ep = g_edge_raw;
        for (int e = rs + lane; e < re; e += 32) {
            int s = __ldg(ep + e);                    // coalesced 4B
            accum_row(in, s, 1.0f, true, acc);
        }
    } else {
        const int2* ep = (const int2*)g_edge_raw;
        for (int e = rs + lane; e < re; e += 32) {
            int2 p = __ldg(ep + e);                   // coalesced 8B
            accum_row(in, p.x, __int_as_float(p.y), false, acc);
        }
    }

    float (*rp)[HID + 1] = red[wid];
    #pragma unroll
    for (int j = 0; j < HID; j++) rp[lane][j] = acc[j];
    __syncwarp();

    if (lane < HID) {
        float s = 0.0f;
        #pragma unroll
        for (int l = 0; l < 32; l++) s += rp[l][lane];
        g_agg[(size_t)n * HID + lane] = s;            // coalesced 80B per warp
    }
}

// ---------------- node MLP; mode 2 fuses global pooling ---------------------
// mode: 0 -> bufB(fp16), 1 -> bufA(fp16), 2 -> pooled atomics (no row output)
__global__ __launch_bounds__(128) void k_mlp(const float* __restrict__ ba,
                                             const float* __restrict__ Wb,
                                             const float* __restrict__ bb,
                                             const float* __restrict__ Wn,
                                             const void* __restrict__ batch_v,
                                             int mode) {
    __shared__ float sWb[HID * HID], sWn[HID * HID], sba[HID], sbb[HID];
    int tid = threadIdx.x;
    for (int i = tid; i < HID * HID; i += 128) {
        sWb[i] = Wb[i];
        sWn[i] = Wn ? Wn[i] : 0.0f;
    }
    if (tid < HID) { sba[tid] = ba[tid]; sbb[tid] = bb[tid]; }
    __syncthreads();
    int n = blockIdx.x * 128 + tid;
    bool valid = n < N_NODES;
    if (!valid && mode != 2) return;

    float z[HID];
    if (valid) {
        float4 t[5];
        const float4* ag = (const float4*)(g_agg + (size_t)n * HID);
        #pragma unroll
        for (int i = 0; i < 5; i++) t[i] = __ldg(ag + i);
        float* zt = (float*)t;

        #pragma unroll
        for (int k = 0; k < HID; k++) z[k] = fmaxf(zt[k] + sba[k], 0.0f);

        float z2[HID];
        #pragma unroll
        for (int j = 0; j < HID; j++) {
            float a = sbb[j];
            #pragma unroll
            for (int k = 0; k < HID; k++) a += z[k] * sWb[k * HID + j];
            z2[j] = fmaxf(a, 0.0f);
        }

        float ss = 0.0f;
        #pragma unroll
        for (int k = 0; k < HID; k++) ss += z2[k] * z2[k];
        float inv = 1.0f / fmaxf(sqrtf(ss), EPS_NORM);
        #pragma unroll
        for (int k = 0; k < HID; k++) z[k] = fmaxf(z2[k] * inv, 0.0f);  // h
    } else {
        #pragma unroll
        for (int k = 0; k < HID; k++) z[k] = 0.0f;
    }

    if (mode != 2) {
        float o[HID];
        #pragma unroll
        for (int j = 0; j < HID; j++) {
            float a = 0.0f;
            #pragma unroll
            for (int k = 0; k < HID; k++) a += z[k] * sWn[k * HID + j];
            o[j] = a;
        }
        store_row_fp16((mode == 0) ? g_bufB : g_bufA, n, o);
        return;
    }

    // ---- fused global max/mean pooling (batch is sorted by graph) ----
    int g = -1;
    if (valid) {
        if (g_is64) g = (int)((const long long*)batch_v)[n];
        else        g = ((const int*)batch_v)[n];
    }
    const unsigned m = 0xffffffffu;
    int g0 = __shfl_sync(m, g, 0);
    bool uni = __all_sync(m, g == g0) && (g0 >= 0);
    int lane = tid & 31;

    if (uni) {
        #pragma unroll
        for (int f = 0; f < HID; f++) {
            float s = z[f], mx = z[f];
            #pragma unroll
            for (int off = 16; off > 0; off >>= 1) {
                s += __shfl_xor_sync(m, s, off);
                mx = fmaxf(mx, __shfl_xor_sync(m, mx, off));
            }
            if (lane == 0) {
                atomicAdd(&g_psum[g0 * HID + f], s);
                atomicMax((int*)&g_pmax[g0 * HID + f], __float_as_int(mx));  // h >= 0
            }
        }
        if (lane == 0) atomicAdd(&g_cnt[g0], 32.0f);
    } else if (valid) {
        #pragma unroll
        for (int f = 0; f < HID; f++) {
            atomicAdd(&g_psum[g * HID + f], z[f]);
            atomicMax((int*)&g_pmax[g * HID + f], __float_as_int(z[f]));
        }
        atomicAdd(&g_cnt[g], 1.0f);
    }
}

__global__ void k_final(const float* __restrict__ Wlin, const float* __restrict__ blin,
                        float* __restrict__ out) {
    int idx = blockIdx.x * blockDim.x + threadIdx.x;
    if (idx >= N_GRAPHS * N_CLASSES) return;
    int gph = idx / N_CLASSES, c = idx % N_CLASSES;
    float cnt = g_cnt[gph];
    float icnt = 1.0f / fmaxf(cnt, 1.0f);
    float acc = __ldg(blin + c);
    #pragma unroll
    for (int k = 0; k < HID; k++) {
        float mx = (cnt > 0.0f) ? g_pmax[gph * HID + k] : 0.0f;
        float mean = g_psum[gph * HID + k] * icnt;
        acc += mx * __ldg(Wlin + k * N_CLASSES + c)
             + mean * __ldg(Wlin + (HID + k) * N_CLASSES + c);
    }
    out[idx] = acc;
}

// ---------------- launch ----------------------------------------------------
extern "C" void kernel_launch(void* const* d_in, const int* in_sizes, int n_in,
                              void* d_out, int out_size) {
    const float* x    = (const float*)d_in[0];
    const void*  ei   = d_in[1];
    const void*  batch= d_in[2];
    const float* ew   = (const float*)d_in[3];
    const float* W1a  = (const float*)d_in[4];
    const float* b1a  = (const float*)d_in[5];
    const float* W1b  = (const float*)d_in[6];
    const float* b1b  = (const float*)d_in[7];
    const float* W2a  = (const float*)d_in[8];
    const float* b2a  = (const float*)d_in[9];
    const float* W2b  = (const float*)d_in[10];
    const float* b2b  = (const float*)d_in[11];
    const float* W3a  = (const float*)d_in[12];
    const float* b3a  = (const float*)d_in[13];
    const float* W3b  = (const float*)d_in[14];
    const float* b3b  = (const float*)d_in[15];
    const float* Wlin = (const float*)d_in[16];
    const float* blin = (const float*)d_in[17];
    float* out = (float*)d_out;

    const int eg = (N_EDGES + 255) / 256;
    const int ng = (N_NODES + 255) / 256;
    const int ag = (N_NODES + AW - 1) / AW;
    const int mg = (N_NODES + 127) / 128;
    const int gg = (N_NODES + 255) / 256;

    k_init<<<ng, 256>>>(ei);
    k_hist<<<eg, 256>>>(ei, ew);
    k_gemm_in<<<gg, 256>>>(x, W1a);
    k_scan1<<<SCAN_B, 1024>>>();
    k_scan2<<<1, 32>>>();
    k_scan3<<<SCAN_B, 1024>>>();
    k_fill<<<eg, 256>>>(ei, ew);

    // three layers: agg (3-load fp16 gather) + node MLP (fp32); layer 3 fuses pooling
    k_agg<<<ag, AW * 32>>>(0);  k_mlp<<<mg, 128>>>(b1a, W1b, b1b, W2a, nullptr, 0);
    k_agg<<<ag, AW * 32>>>(1);  k_mlp<<<mg, 128>>>(b2a, W2b, b2b, W3a, nullptr, 1);
    k_agg<<<ag, AW * 32>>>(2);  k_mlp<<<mg, 128>>>(b3a, W3b, b3b, nullptr, batch, 2);

    k_final<<<2, 640>>>(Wlin, blin, out);
}

// round 12
// speedup vs baseline: 2.1008x; 1.2773x over previous
#include <cuda_runtime.h>
#include <cuda_fp16.h>
#include <cstdint>

#define N_NODES 100000
#define N_EDGES 3200000
#define F_IN 64
#define HID 20
#define H2P 12                              // half2 per padded row (48B)
#define N_GRAPHS 128
#define N_CLASSES 10
#define EPS_NORM 1e-12f
#define SCAN_B ((N_NODES + 1023) / 1024)    // 98

// ---------------- scratch (device globals) ---------------------------------
__device__ __align__(16) __half2 g_bufA[N_NODES * H2P];  // fp16 rows padded to 48B
__device__ __align__(16) __half2 g_bufB[N_NODES * H2P];
__device__ __align__(16) float g_agg[N_NODES * HID];
__device__ __align__(16) int g_edge_raw[2 * N_EDGES];    // int2 (s,w) or int (s) per edge
__device__ int g_deg[N_NODES];
__device__ int g_rowptr[N_NODES + 1];
__device__ int g_cursor[N_NODES];
__device__ int g_bsum[128];
__device__ int g_boff[128];
__device__ float g_pmax[N_GRAPHS * HID];
__device__ float g_psum[N_GRAPHS * HID];
__device__ float g_cnt[N_GRAPHS];
__device__ int   g_is64;
__device__ int   g_wuni;                                 // 1 if all edge weights == 1.0f

// ---------------- init: dtype probe + zero deg + zero pool ------------------
__global__ void k_init(const void* __restrict__ ei) {
    int i = blockIdx.x * blockDim.x + threadIdx.x;
    if (i == 0) {
        const long long* p = (const long long*)ei;
        bool ok = true;
        #pragma unroll
        for (int q = 0; q < 16; q++) {
            long long v = p[q];
            if (v < 0 || v >= (long long)N_NODES) ok = false;
        }
        g_is64 = ok ? 1 : 0;
        g_wuni = 1;
    }
    if (i < N_NODES) g_deg[i] = 0;
    if (i < N_GRAPHS * HID) { g_pmax[i] = 0.0f; g_psum[i] = 0.0f; }
    if (i < N_GRAPHS) g_cnt[i] = 0.0f;
}

// ---------------- CSR build -------------------------------------------------
__global__ void k_hist(const void* __restrict__ ei, const float* __restrict__ w) {
    int e = blockIdx.x * blockDim.x + threadIdx.x;
    if (e >= N_EDGES) return;
    int d;
    if (g_is64) d = (int)((const long long*)ei)[N_EDGES + e];
    else        d = ((const int*)ei)[N_EDGES + e];
    atomicAdd(&g_deg[d], 1);
    if (w[e] != 1.0f) g_wuni = 0;   // benign race: all writers store 0
}

__global__ void k_scan1() {
    __shared__ int s[1024];
    int t = threadIdx.x;
    int i = blockIdx.x * 1024 + t;
    s[t] = (i < N_NODES) ? g_deg[i] : 0;
    __syncthreads();
    #pragma unroll
    for (int off = 512; off > 0; off >>= 1) {
        if (t < off) s[t] += s[t + off];
        __syncthreads();
    }
    if (t == 0) g_bsum[blockIdx.x] = s[0];
}

__global__ void k_scan2() {
    if (threadIdx.x == 0) {
        int run = 0;
        for (int i = 0; i < SCAN_B; i++) {
            g_boff[i] = run;
            run += g_bsum[i];
        }
        g_rowptr[N_NODES] = run;
    }
}

__global__ void k_scan3() {
    __shared__ int s[1024];
    int t = threadIdx.x;
    int i = blockIdx.x * 1024 + t;
    int v = (i < N_NODES) ? g_deg[i] : 0;
    s[t] = v;
    __syncthreads();
    #pragma unroll
    for (int off = 1; off < 1024; off <<= 1) {
        int u = (t >= off) ? s[t - off] : 0;
        __syncthreads();
        s[t] += u;
        __syncthreads();
    }
    if (i < N_NODES) {
        int ex = s[t] - v + g_boff[blockIdx.x];
        g_rowptr[i] = ex;
        g_cursor[i] = ex;
    }
}

__global__ void k_fill(const void* __restrict__ ei, const float* __restrict__ w) {
    int e = blockIdx.x * blockDim.x + threadIdx.x;
    if (e >= N_EDGES) return;
    int s, d;
    if (g_is64) {
        const long long* p = (const long long*)ei;
        s = (int)p[e]; d = (int)p[N_EDGES + e];
    } else {
        const int* p = (const int*)ei;
        s = p[e]; d = p[N_EDGES + e];
    }
    int pos = atomicAdd(&g_cursor[d], 1);
    if (g_wuni) {
        g_edge_raw[pos] = s;                          // src only, 4B
    } else {
        ((int2*)g_edge_raw)[pos] = make_int2(s, __float_as_int(w[e]));
    }
}

// ---------------- helpers ---------------------------------------------------
__device__ __forceinline__ void store_row_fp16(__half2* base, int n, const float* o) {
    // 20 floats -> 10 half2 + 2 zero half2 padding -> 3 x 16B stores (48B row)
    uint4* op = (uint4*)(base + (size_t)n * H2P);
    unsigned hp[12];
    #pragma unroll
    for (int q = 0; q < 10; q++) {
        __half2 h = __floats2half2_rn(o[2 * q], o[2 * q + 1]);
        hp[q] = *(unsigned*)&h;
    }
    hp[10] = 0u; hp[11] = 0u;
    op[0] = make_uint4(hp[0], hp[1], hp[2], hp[3]);
    op[1] = make_uint4(hp[4], hp[5], hp[6], hp[7]);
    op[2] = make_uint4(hp[8], hp[9], hp[10], hp[11]);
}

// ---------------- layer-1 input GEMM: bufA = fp16(x @ W1a) ------------------
__global__ __launch_bounds__(256) void k_gemm_in(const float* __restrict__ x,
                                                 const float* __restrict__ W) {
    __shared__ float sW[F_IN * HID];   // 5.1 KB
    int tid = threadIdx.x;
    for (int i = tid; i < F_IN * HID; i += 256) sW[i] = W[i];
    __syncthreads();
    int n = blockIdx.x * 256 + tid;
    if (n >= N_NODES) return;

    const float4* xr = (const float4*)(x + (size_t)n * F_IN);

    float acc[HID];
    #pragma unroll
    for (int j = 0; j < HID; j++) acc[j] = 0.0f;

    #pragma unroll
    for (int c = 0; c < 4; c++) {
        float4 xv[4];
        #pragma unroll
        for (int q = 0; q < 4; q++) xv[q] = __ldg(xr + c * 4 + q);
        const float* xs = (const float*)xv;
        #pragma unroll
        for (int kk = 0; kk < 16; kk++) {
            int k = c * 16 + kk;
            float xk = xs[kk];
            const float4* wr = (const float4*)&sW[k * HID];
            #pragma unroll
            for (int q = 0; q < 5; q++) {
                float4 wv = wr[q];
                acc[4 * q + 0] += xk * wv.x;
                acc[4 * q + 1] += xk * wv.y;
                acc[4 * q + 2] += xk * wv.z;
                acc[4 * q + 3] += xk * wv.w;
            }
        }
    }
    store_row_fp16(g_bufA, n, acc);
}

// ---------------- aggregation: warp/node, 3-lane cooperative row gather -----
// 10 groups x 3 lanes per warp. Group g handles edges rs+g, rs+g+10, ...
// Lane role r loads bytes [16r, 16r+16) of the 48B row -> lanes of a group hit
// the same 128B line in the same LDG -> ~1.33 wavefronts/edge instead of 3.
// mode selects input: 0,2 -> bufA ; 1 -> bufB.  Output: g_agg (fp32).
#define AW 8
__global__ __launch_bounds__(AW * 32) void k_agg(int mode) {
    __shared__ float red[AW][32][9];   // [warp][lane][8 feats + pad]
    int tid = threadIdx.x;
    int wid = tid >> 5, lane = tid & 31;
    int n = blockIdx.x * AW + wid;
    if (n >= N_NODES) return;

    const char* in = (const char*)((mode == 1) ? g_bufB : g_bufA);
    bool uni = (g_wuni != 0);
    int rs = __ldg(&g_rowptr[n]);
    int re = __ldg(&g_rowptr[n + 1]);

    int grp  = lane / 3;           // 0..9 valid; 10 for lanes 30,31
    int role = lane - grp * 3;     // 0..2
    bool active = grp < 10;

    float acc[8];
    #pragma unroll
    for (int j = 0; j < 8; j++) acc[j] = 0.0f;

    if (active) {
        if (uni) {
            const int* ep = g_edge_raw;
            for (int e = rs + grp; e < re; e += 10) {
                int s = __ldg(ep + e);                       // broadcast within group
                uint4 v = __ldg((const uint4*)(in + (size_t)s * 48) + role);
                unsigned hp[4] = {v.x, v.y, v.z, v.w};
                #pragma unroll
                for (int q = 0; q < 4; q++) {
                    float2 f = __half22float2(*(__half2*)&hp[q]);
                    acc[2 * q + 0] += f.x;
                    acc[2 * q + 1] += f.y;
                }
            }
        } else {
            const int2* ep = (const int2*)g_edge_raw;
            for (int e = rs + grp; e < re; e += 10) {
                int2 p = __ldg(ep + e);
                float w = __int_as_float(p.y);
                uint4 v = __ldg((const uint4*)(in + (size_t)p.x * 48) + role);
                unsigned hp[4] = {v.x, v.y, v.z, v.w};
                #pragma unroll
                for (int q = 0; q < 4; q++) {
                    float2 f = __half22float2(*(__half2*)&hp[q]);
                    acc[2 * q + 0] += f.x * w;
                    acc[2 * q + 1] += f.y * w;
                }
            }
        }
    }

    // reduction: feature f = 8*role + j lives in lanes {3g + role}, g = 0..9
    float (*rp)[9] = red[wid];
    #pragma unroll
    for (int j = 0; j < 8; j++) rp[lane][j] = acc[j];
    __syncwarp();

    if (lane < HID) {
        int r = lane >> 3, j = lane & 7;   // feature -> (role, slot)
        float s = 0.0f;
        #pragma unroll
        for (int g = 0; g < 10; g++) s += rp[3 * g + r][j];
        g_agg[(size_t)n * HID + lane] = s;               // coalesced 80B per warp
    }
}

// ---------------- node MLP; mode 2 fuses global pooling ---------------------
// mode: 0 -> bufB(fp16), 1 -> bufA(fp16), 2 -> pooled atomics (no row output)
__global__ __launch_bounds__(128) void k_mlp(const float* __restrict__ ba,
                                             const float* __restrict__ Wb,
                                             const float* __restrict__ bb,
                                             const float* __restrict__ Wn,
                                             const void* __restrict__ batch_v,
                                             int mode) {
    __shared__ float sWb[HID * HID], sWn[HID * HID], sba[HID], sbb[HID];
    int tid = threadIdx.x;
    for (int i = tid; i < HID * HID; i += 128) {
        sWb[i] = Wb[i];
        sWn[i] = Wn ? Wn[i] : 0.0f;
    }
    if (tid < HID) { sba[tid] = ba[tid]; sbb[tid] = bb[tid]; }
    __syncthreads();
    int n = blockIdx.x * 128 + tid;
    bool valid = n < N_NODES;
    if (!valid && mode != 2) return;

    float z[HID];
    if (valid) {
        float4 t[5];
        const float4* ag = (const float4*)(g_agg + (size_t)n * HID);
        #pragma unroll
        for (int i = 0; i < 5; i++) t[i] = __ldg(ag + i);
        float* zt = (float*)t;

        #pragma unroll
        for (int k = 0; k < HID; k++) z[k] = fmaxf(zt[k] + sba[k], 0.0f);

        float z2[HID];
        #pragma unroll
        for (int j = 0; j < HID; j++) {
            float a = sbb[j];
            #pragma unroll
            for (int k = 0; k < HID; k++) a += z[k] * sWb[k * HID + j];
            z2[j] = fmaxf(a, 0.0f);
        }

        float ss = 0.0f;
        #pragma unroll
        for (int k = 0; k < HID; k++) ss += z2[k] * z2[k];
        float inv = 1.0f / fmaxf(sqrtf(ss), EPS_NORM);
        #pragma unroll
        for (int k = 0; k < HID; k++) z[k] = fmaxf(z2[k] * inv, 0.0f);  // h
    } else {
        #pragma unroll
        for (int k = 0; k < HID; k++) z[k] = 0.0f;
    }

    if (mode != 2) {
        float o[HID];
        #pragma unroll
        for (int j = 0; j < HID; j++) {
            float a = 0.0f;
            #pragma unroll
            for (int k = 0; k < HID; k++) a += z[k] * sWn[k * HID + j];
            o[j] = a;
        }
        store_row_fp16((mode == 0) ? g_bufB : g_bufA, n, o);
        return;
    }

    // ---- fused global max/mean pooling (batch is sorted by graph) ----
    int g = -1;
    if (valid) {
        if (g_is64) g = (int)((const long long*)batch_v)[n];
        else        g = ((const int*)batch_v)[n];
    }
    const unsigned m = 0xffffffffu;
    int g0 = __shfl_sync(m, g, 0);
    bool uni = __all_sync(m, g == g0) && (g0 >= 0);
    int lane = tid & 31;

    if (uni) {
        #pragma unroll
        for (int f = 0; f < HID; f++) {
            float s = z[f], mx = z[f];
            #pragma unroll
            for (int off = 16; off > 0; off >>= 1) {
                s += __shfl_xor_sync(m, s, off);
                mx = fmaxf(mx, __shfl_xor_sync(m, mx, off));
            }
            if (lane == 0) {
                atomicAdd(&g_psum[g0 * HID + f], s);
                atomicMax((int*)&g_pmax[g0 * HID + f], __float_as_int(mx));  // h >= 0
            }
        }
        if (lane == 0) atomicAdd(&g_cnt[g0], 32.0f);
    } else if (valid) {
        #pragma unroll
        for (int f = 0; f < HID; f++) {
            atomicAdd(&g_psum[g * HID + f], z[f]);
            atomicMax((int*)&g_pmax[g * HID + f], __float_as_int(z[f]));
        }
        atomicAdd(&g_cnt[g], 1.0f);
    }
}

__global__ void k_final(const float* __restrict__ Wlin, const float* __restrict__ blin,
                        float* __restrict__ out) {
    int idx = blockIdx.x * blockDim.x + threadIdx.x;
    if (idx >= N_GRAPHS * N_CLASSES) return;
    int gph = idx / N_CLASSES, c = idx % N_CLASSES;
    float cnt = g_cnt[gph];
    float icnt = 1.0f / fmaxf(cnt, 1.0f);
    float acc = __ldg(blin + c);
    #pragma unroll
    for (int k = 0; k < HID; k++) {
        float mx = (cnt > 0.0f) ? g_pmax[gph * HID + k] : 0.0f;
        float mean = g_psum[gph * HID + k] * icnt;
        acc += mx * __ldg(Wlin + k * N_CLASSES + c)
             + mean * __ldg(Wlin + (HID + k) * N_CLASSES + c);
    }
    out[idx] = acc;
}

// ---------------- launch ----------------------------------------------------
extern "C" void kernel_launch(void* const* d_in, const int* in_sizes, int n_in,
                              void* d_out, int out_size) {
    const float* x    = (const float*)d_in[0];
    const void*  ei   = d_in[1];
    const void*  batch= d_in[2];
    const float* ew   = (const float*)d_in[3];
    const float* W1a  = (const float*)d_in[4];
    const float* b1a  = (const float*)d_in[5];
    const float* W1b  = (const float*)d_in[6];
    const float* b1b  = (const float*)d_in[7];
    const float* W2a  = (const float*)d_in[8];
    const float* b2a  = (const float*)d_in[9];
    const float* W2b  = (const float*)d_in[10];
    const float* b2b  = (const float*)d_in[11];
    const float* W3a  = (const float*)d_in[12];
    const float* b3a  = (const float*)d_in[13];
    const float* W3b  = (const float*)d_in[14];
    const float* b3b  = (const float*)d_in[15];
    const float* Wlin = (const float*)d_in[16];
    const float* blin = (const float*)d_in[17];
    float* out = (float*)d_out;

    const int eg = (N_EDGES + 255) / 256;
    const int ng = (N_NODES + 255) / 256;
    const int ag = (N_NODES + AW - 1) / AW;
    const int mg = (N_NODES + 127) / 128;
    const int gg = (N_NODES + 255) / 256;

    k_init<<<ng, 256>>>(ei);
    k_hist<<<eg, 256>>>(ei, ew);
    k_gemm_in<<<gg, 256>>>(x, W1a);
    k_scan1<<<SCAN_B, 1024>>>();
    k_scan2<<<1, 32>>>();
    k_scan3<<<SCAN_B, 1024>>>();
    k_fill<<<eg, 256>>>(ei, ew);

    // three layers: agg (3-lane cooperative gather) + node MLP; layer 3 fuses pooling
    k_agg<<<ag, AW * 32>>>(0);  k_mlp<<<mg, 128>>>(b1a, W1b, b1b, W2a, nullptr, 0);
    k_agg<<<ag, AW * 32>>>(1);  k_mlp<<<mg, 128>>>(b2a, W2b, b2b, W3a, nullptr, 1);
    k_agg<<<ag, AW * 32>>>(2);  k_mlp<<<mg, 128>>>(b3a, W3b, b3b, nullptr, batch, 2);

    k_final<<<2, 640>>>(Wlin, blin, out);
}